// round 8
// baseline (speedup 1.0000x reference)
#include <cuda_runtime.h>
#include <cuda_fp16.h>
#include <cstdint>

#define Bsz     32768
#define Dd      1024
#define Cc      40
#define CT      80            // 40 fwd + 40 rev output columns
#define RB      128           // rows (M) per CTA -> 256 CTAs
#define THREADS 256           // 8 warps: 4 M-warps x 2 N-warps
#define KC      32            // k per chunk
#define NCH     (Dd / KC)     // 32

// fp16 stage: A 128 rows x 32 f16 @ 80B stride = 10240B, B 80 rows @ 80B = 6400B
#define AROWB   80
#define BOFF    10240
#define STAGE_B 16640
#define OFFST   1024          // stage 0 byte offset
// GEMM needs 1024 + 2*16640 = 34304 B; epilogue overlay needs more:
#define BROW    81
#define EPI_BASE_F 256
#define EPI_WT_F   (EPI_BASE_F + RB * BROW)       // 256+10368
#define EPI_BB_F   (EPI_WT_F + 2 * Cc * Cc)
#define SMEM_BYTES ((EPI_BB_F + 2 * Cc) * 4)      // 55616 B

__device__ __half Wh[CT * Dd];   // fp16 copy of GEMM part of [W;W_rev]

extern __shared__ float smf[];

// pack two fp32 -> f16x2 (lo in low half): PTX first source fills HIGH half
__device__ __forceinline__ uint32_t pk(float lo, float hi) {
    uint32_t r;
    asm("cvt.rn.f16x2.f32 %0, %1, %2;" : "=r"(r) : "f"(hi), "f"(lo));
    return r;
}

__device__ __forceinline__ void mma_16x8x16(float* d, const uint32_t* a,
                                            const uint32_t* bf) {
    asm volatile(
        "mma.sync.aligned.m16n8k16.row.col.f32.f16.f16.f32 "
        "{%0,%1,%2,%3}, {%4,%5,%6,%7}, {%8,%9}, {%0,%1,%2,%3};"
        : "+f"(d[0]), "+f"(d[1]), "+f"(d[2]), "+f"(d[3])
        : "r"(a[0]), "r"(a[1]), "r"(a[2]), "r"(a[3]), "r"(bf[0]), "r"(bf[1]));
}

__device__ __forceinline__ void ldsm4(uint32_t* r, uint32_t a) {
    asm volatile("ldmatrix.sync.aligned.m8n8.x4.shared.b16 {%0,%1,%2,%3}, [%4];"
                 : "=r"(r[0]), "=r"(r[1]), "=r"(r[2]), "=r"(r[3]) : "r"(a));
}
__device__ __forceinline__ void ldsm2(uint32_t* r, uint32_t a) {
    asm volatile("ldmatrix.sync.aligned.m8n8.x2.shared.b16 {%0,%1}, [%2];"
                 : "=r"(r[0]), "=r"(r[1]) : "r"(a));
}

__global__ void convert_w(const float* __restrict__ W,
                          const float* __restrict__ Wr) {
    const int idx = blockIdx.x * 256 + threadIdx.x;
    if (idx < CT * Dd) {
        const int r = idx >> 10, k = idx & 1023;
        const float* Wp = (r < Cc) ? W  + (size_t)r        * (Dd + Cc)
                                   : Wr + (size_t)(r - Cc) * (Dd + Cc);
        Wh[idx] = __float2half_rn(Wp[k]);
    }
}

__global__ void __launch_bounds__(THREADS, 2)
bichain_ldsm(const float* __restrict__ src,
             const float* __restrict__ W,  const float* __restrict__ b,
             const float* __restrict__ Wr, const float* __restrict__ br,
             float* __restrict__ out) {
    const int tid  = threadIdx.x;
    const int warp = tid >> 5;
    const int lane = tid & 31;
    const int row0 = blockIdx.x * RB;

    uint32_t smb;
    asm("{ .reg .u64 t; cvta.to.shared.u64 t, %1; cvt.u32.u64 %0, t; }"
        : "=r"(smb) : "l"(smf));

    // ---- producer A: each thread owns 16 floats of one row-chunk ----
    const int arow  = tid & 127;
    const int ahalf = tid >> 7;
    const float* gA = src + (size_t)(row0 + arow) * Dd + ahalf * 16;
    const uint32_t stsoff = (uint32_t)(arow * AROWB + ahalf * 32);

    float4 rcur[4], rnxt[4];
    auto ldgA = [&](int ch, float4* rr) {
        const float4* p = (const float4*)(gA + ch * KC);
        rr[0] = p[0]; rr[1] = p[1]; rr[2] = p[2]; rr[3] = p[3];
    };
    auto stsA = [&](const float4* rr, uint32_t sbase) {
        uint32_t q0 = pk(rr[0].x, rr[0].y), q1 = pk(rr[0].z, rr[0].w);
        uint32_t q2 = pk(rr[1].x, rr[1].y), q3 = pk(rr[1].z, rr[1].w);
        uint32_t q4 = pk(rr[2].x, rr[2].y), q5 = pk(rr[2].z, rr[2].w);
        uint32_t q6 = pk(rr[3].x, rr[3].y), q7 = pk(rr[3].z, rr[3].w);
        asm volatile("st.shared.v4.b32 [%0], {%1,%2,%3,%4};"
                     :: "r"(sbase + stsoff), "r"(q0), "r"(q1), "r"(q2), "r"(q3));
        asm volatile("st.shared.v4.b32 [%0], {%1,%2,%3,%4};"
                     :: "r"(sbase + stsoff + 16), "r"(q4), "r"(q5), "r"(q6), "r"(q7));
    };
    // ---- producer B: fp16 W rows via cp.async (320 x 16B per chunk) ----
    auto cpB = [&](int ch, uint32_t sbase) {
        #pragma unroll
        for (int i = 0; i < 2; ++i) {
            const int idx = tid + i * 256;
            if (idx < CT * 4) {
                const int r = idx >> 2, seg = idx & 3;
                const __half* g = Wh + (size_t)r * Dd + ch * KC + seg * 8;
                const uint32_t d = sbase + BOFF + (uint32_t)(r * AROWB + seg * 16);
                asm volatile("cp.async.ca.shared.global [%0], [%1], 16;"
                             :: "r"(d), "l"(g));
            }
        }
        asm volatile("cp.async.commit_group;");
    };

    // ---- consumer lane offsets (stage-relative, bytes) ----
    const int mw = warp >> 1, nw = warp & 1;
    const int g8 = lane >> 3, i8 = lane & 7;
    uint32_t aoff[2][2], boff[2][2], boffc[2];
    #pragma unroll
    for (int mt = 0; mt < 2; ++mt)
        #pragma unroll
        for (int kk = 0; kk < 2; ++kk)
            aoff[mt][kk] = (uint32_t)((mw * 32 + mt * 16 + (g8 & 1) * 8 + i8) * AROWB
                                      + (g8 >> 1) * 16 + kk * 32);
    #pragma unroll
    for (int p = 0; p < 2; ++p)
        #pragma unroll
        for (int kk = 0; kk < 2; ++kk)
            boff[p][kk] = (uint32_t)(BOFF + (nw * 40 + p * 16 + (g8 >> 1) * 8 + i8) * AROWB
                                     + (g8 & 1) * 16 + kk * 32);
    {
        const int l2g = (lane & 15) >> 3;
        #pragma unroll
        for (int kk = 0; kk < 2; ++kk)
            boffc[kk] = (uint32_t)(BOFF + (nw * 40 + 32 + i8) * AROWB
                                   + l2g * 16 + kk * 32);
    }

    float acc[2][5][4];
    #pragma unroll
    for (int mt = 0; mt < 2; ++mt)
        #pragma unroll
        for (int t = 0; t < 5; ++t)
            #pragma unroll
            for (int e = 0; e < 4; ++e) acc[mt][t][e] = 0.f;

    const uint32_t sb0 = smb + OFFST;
    const uint32_t sb1 = smb + OFFST + STAGE_B;

    // ---- prologue ----
    ldgA(0, rcur);
    cpB(0, sb0);
    stsA(rcur, sb0);
    ldgA(1, rcur);
    cpB(1, sb1);
    asm volatile("cp.async.wait_group 1;");
    __syncthreads();
    // invariant: stage0 = chunk0 ready; rcur = A(1); B(1) in flight -> stage1

    for (int ch = 0; ch < NCH; ++ch) {
        const uint32_t sb = (ch & 1) ? sb1 : sb0;
        const uint32_t so = (ch & 1) ? sb0 : sb1;

        if (ch + 2 < NCH) ldgA(ch + 2, rnxt);
        if (ch + 1 < NCH) stsA(rcur, so);      // stage 'other' free since prev sync

        #pragma unroll
        for (int kk = 0; kk < 2; ++kk) {
            uint32_t a0[4], a1[4], q0[4], q1[4], q2[2];
            ldsm4(a0, sb + aoff[0][kk]);
            ldsm4(a1, sb + aoff[1][kk]);
            ldsm4(q0, sb + boff[0][kk]);
            ldsm4(q1, sb + boff[1][kk]);
            ldsm2(q2, sb + boffc[kk]);
            mma_16x8x16(acc[0][0], a0, q0);
            mma_16x8x16(acc[0][1], a0, q0 + 2);
            mma_16x8x16(acc[0][2], a0, q1);
            mma_16x8x16(acc[0][3], a0, q1 + 2);
            mma_16x8x16(acc[0][4], a0, q2);
            mma_16x8x16(acc[1][0], a1, q0);
            mma_16x8x16(acc[1][1], a1, q0 + 2);
            mma_16x8x16(acc[1][2], a1, q1);
            mma_16x8x16(acc[1][3], a1, q1 + 2);
            mma_16x8x16(acc[1][4], a1, q2);
        }

        if (ch + 1 < NCH) asm volatile("cp.async.wait_group 0;");
        __syncthreads();                       // chunk ch consumed; chunk ch+1 complete
        if (ch + 2 < NCH) cpB(ch + 2, sb);     // refill just-freed stage
        #pragma unroll
        for (int i = 0; i < 4; ++i) rcur[i] = rnxt[i];
    }

    // ---- accumulators -> smem bases[128][81] ----
    const int qr = lane >> 2, qc = lane & 3;
    float* bases = smf + EPI_BASE_F;
    #pragma unroll
    for (int mt = 0; mt < 2; ++mt) {
        const int r = mw * 32 + mt * 16 + qr;
        #pragma unroll
        for (int t = 0; t < 5; ++t) {
            const int c = nw * 40 + t * 8 + qc * 2;
            bases[(r    ) * BROW + c    ] = acc[mt][t][0];
            bases[(r    ) * BROW + c + 1] = acc[mt][t][1];
            bases[(r + 8) * BROW + c    ] = acc[mt][t][2];
            bases[(r + 8) * BROW + c + 1] = acc[mt][t][3];
        }
    }

    // chain tail weights W[:,1024:1064] + biases (fp32 originals)
    float* wt = smf + EPI_WT_F;
    float* bb = smf + EPI_BB_F;
    for (int idx = tid; idx < 2 * Cc * Cc; idx += THREADS) {
        const int chn = idx / (Cc * Cc);
        const int rem = idx - chn * Cc * Cc;
        const int i = rem / Cc, j = rem % Cc;
        const float* Wp = chn ? Wr : W;
        wt[idx] = Wp[(size_t)i * (Dd + Cc) + Dd + j];
    }
    if (tid < 2 * Cc) bb[tid] = (tid < Cc) ? b[tid] : br[tid - Cc];
    __syncthreads();

    // ---- sequential chains: 256 threads = 128 rows x 2 chains ----
    {
        const int row = tid >> 1, chn = tid & 1;
        float* my        = bases + row * BROW + chn * Cc;
        const float* wtc = wt + chn * Cc * Cc;
        const float* bbc = bb + chn * Cc;
        float s[Cc];
        #pragma unroll
        for (int i = 0; i < Cc; ++i) {
            float x = my[i] + bbc[i];
            #pragma unroll
            for (int j = 0; j < i; ++j)
                x = fmaf(s[j], wtc[i * Cc + j], x);
            s[i] = 1.0f / (1.0f + __expf(-x));
            my[i] = s[i];
        }
    }
    __syncthreads();

    // ---- combine fwd + reversed rev, coalesced store ----
    #pragma unroll
    for (int it = 0; it < (RB * Cc) / THREADS; ++it) {   // 20
        const int idx = tid + it * THREADS;
        const int r = idx / Cc, c = idx - r * Cc;
        const float vf = bases[r * BROW + c];
        const float vr = bases[r * BROW + Cc + (Cc - 1 - c)];
        out[(size_t)(row0 + r) * Cc + c] = 0.5f * (vf + vr);
    }
}

extern "C" void kernel_launch(void* const* d_in, const int* in_sizes, int n_in,
                              void* d_out, int out_size) {
    const float* src = (const float*)d_in[0];
    // d_in[1] = attn_mask (unused)
    const float* W   = (const float*)d_in[2];
    const float* b   = (const float*)d_in[3];
    const float* Wr  = (const float*)d_in[4];
    const float* br  = (const float*)d_in[5];
    float* out = (float*)d_out;

    convert_w<<<(CT * Dd + 255) / 256, 256>>>(W, Wr);
    cudaFuncSetAttribute(bichain_ldsm,
                         cudaFuncAttributeMaxDynamicSharedMemorySize, SMEM_BYTES);
    bichain_ldsm<<<Bsz / RB, THREADS, SMEM_BYTES>>>(src, W, b, Wr, br, out);
}

// round 9
// speedup vs baseline: 1.0004x; 1.0004x over previous
#include <cuda_runtime.h>
#include <cuda_fp16.h>
#include <cstdint>

#define Bsz     32768
#define Dd      1024
#define Cc      40
#define CT      80            // 40 fwd + 40 rev output columns
#define RB      128           // rows (M) per CTA -> 256 CTAs
#define THREADS 256           // 8 warps: 4 M-warps x 2 N-warps
#define KC      32            // k per chunk
#define NCH     (Dd / KC)     // 32
#define NBST    4             // B ring depth

#define AROWB   80            // bytes per fp16 row (64 data + 16 pad) -> LDSM conflict-free
#define A_STAGE 10240         // 128 rows * 80B
#define B_STAGE 6400          // 80 rows * 80B
#define OFF_A0  1024
#define OFF_B0  (OFF_A0 + 2 * A_STAGE)          // 21504; B ring: 4 x 6400 -> end 47104

#define BROW    81
#define EPI_BASE_F 256
#define EPI_WT_F   (EPI_BASE_F + RB * BROW)
#define EPI_BB_F   (EPI_WT_F + 2 * Cc * Cc)
#define SMEM_BYTES ((EPI_BB_F + 2 * Cc) * 4)    // 55616 B -> 2 CTAs/SM

__device__ __half Wh[CT * Dd];   // fp16 copy of GEMM part of [W;W_rev]

extern __shared__ float smf[];

__device__ __forceinline__ uint32_t pk(float lo, float hi) {
    uint32_t r;
    asm("cvt.rn.f16x2.f32 %0, %1, %2;" : "=r"(r) : "f"(hi), "f"(lo));
    return r;
}

__device__ __forceinline__ void mma_16x8x16(float* d, const uint32_t* a,
                                            const uint32_t* bf) {
    asm volatile(
        "mma.sync.aligned.m16n8k16.row.col.f32.f16.f16.f32 "
        "{%0,%1,%2,%3}, {%4,%5,%6,%7}, {%8,%9}, {%0,%1,%2,%3};"
        : "+f"(d[0]), "+f"(d[1]), "+f"(d[2]), "+f"(d[3])
        : "r"(a[0]), "r"(a[1]), "r"(a[2]), "r"(a[3]), "r"(bf[0]), "r"(bf[1]));
}

__device__ __forceinline__ void ldsm4(uint32_t* r, uint32_t a) {
    asm volatile("ldmatrix.sync.aligned.m8n8.x4.shared.b16 {%0,%1,%2,%3}, [%4];"
                 : "=r"(r[0]), "=r"(r[1]), "=r"(r[2]), "=r"(r[3]) : "r"(a));
}
__device__ __forceinline__ void ldsm2(uint32_t* r, uint32_t a) {
    asm volatile("ldmatrix.sync.aligned.m8n8.x2.shared.b16 {%0,%1}, [%2];"
                 : "=r"(r[0]), "=r"(r[1]) : "r"(a));
}

__global__ void convert_w(const float* __restrict__ W,
                          const float* __restrict__ Wr) {
    const int idx = blockIdx.x * 256 + threadIdx.x;
    if (idx < CT * Dd) {
        const int r = idx >> 10, k = idx & 1023;
        const float* Wp = (r < Cc) ? W  + (size_t)r        * (Dd + Cc)
                                   : Wr + (size_t)(r - Cc) * (Dd + Cc);
        Wh[idx] = __float2half_rn(Wp[k]);
    }
}

__global__ void __launch_bounds__(THREADS, 2)
bichain_p4(const float* __restrict__ src,
           const float* __restrict__ W,  const float* __restrict__ b,
           const float* __restrict__ Wr, const float* __restrict__ br,
           float* __restrict__ out) {
    const int tid  = threadIdx.x;
    const int warp = tid >> 5;
    const int lane = tid & 31;
    const int row0 = blockIdx.x * RB;

    uint32_t smb;
    asm("{ .reg .u64 t; cvta.to.shared.u64 t, %1; cvt.u32.u64 %0, t; }"
        : "=r"(smb) : "l"(smf));

    // ---- producer A: each thread owns 16 floats of one row-chunk ----
    const int arow  = tid & 127;
    const int ahalf = tid >> 7;
    const float* gA = src + (size_t)(row0 + arow) * Dd + ahalf * 16;
    const uint32_t stsoff = (uint32_t)(arow * AROWB + ahalf * 32);

    float4 rcur[4], rnxt[4];
    auto ldgA = [&](int ch, float4* rr) {
        const float4* p = (const float4*)(gA + ch * KC);
        rr[0] = p[0]; rr[1] = p[1]; rr[2] = p[2]; rr[3] = p[3];
    };
    auto stsA = [&](const float4* rr, uint32_t sbase) {
        uint32_t q0 = pk(rr[0].x, rr[0].y), q1 = pk(rr[0].z, rr[0].w);
        uint32_t q2 = pk(rr[1].x, rr[1].y), q3 = pk(rr[1].z, rr[1].w);
        uint32_t q4 = pk(rr[2].x, rr[2].y), q5 = pk(rr[2].z, rr[2].w);
        uint32_t q6 = pk(rr[3].x, rr[3].y), q7 = pk(rr[3].z, rr[3].w);
        asm volatile("st.shared.v4.b32 [%0], {%1,%2,%3,%4};"
                     :: "r"(sbase + stsoff), "r"(q0), "r"(q1), "r"(q2), "r"(q3));
        asm volatile("st.shared.v4.b32 [%0], {%1,%2,%3,%4};"
                     :: "r"(sbase + stsoff + 16), "r"(q4), "r"(q5), "r"(q6), "r"(q7));
    };
    // ---- producer B: fp16 W rows via cp.async into 4-deep ring ----
    // ALWAYS commits a group (empty past NCH) so group accounting stays uniform.
    auto cpB = [&](int ch) {
        if (ch < NCH) {
            const uint32_t sbase = smb + OFF_B0 + (uint32_t)(ch % NBST) * B_STAGE;
            #pragma unroll
            for (int i = 0; i < 2; ++i) {
                const int idx = tid + i * 256;
                if (idx < CT * 4) {
                    const int r = idx >> 2, seg = idx & 3;
                    const __half* g = Wh + (size_t)r * Dd + ch * KC + seg * 8;
                    const uint32_t d = sbase + (uint32_t)(r * AROWB + seg * 16);
                    asm volatile("cp.async.ca.shared.global [%0], [%1], 16;"
                                 :: "r"(d), "l"(g));
                }
            }
        }
        asm volatile("cp.async.commit_group;");
    };

    // ---- consumer lane offsets (stage-relative, bytes) ----
    const int mw = warp >> 1, nw = warp & 1;
    const int g8 = lane >> 3, i8 = lane & 7;
    uint32_t aoff[2][2], boff[2][2], boffc[2];
    #pragma unroll
    for (int mt = 0; mt < 2; ++mt)
        #pragma unroll
        for (int kk = 0; kk < 2; ++kk)
            aoff[mt][kk] = (uint32_t)((mw * 32 + mt * 16 + (g8 & 1) * 8 + i8) * AROWB
                                      + (g8 >> 1) * 16 + kk * 32);
    #pragma unroll
    for (int p = 0; p < 2; ++p)
        #pragma unroll
        for (int kk = 0; kk < 2; ++kk)
            boff[p][kk] = (uint32_t)((nw * 40 + p * 16 + (g8 >> 1) * 8 + i8) * AROWB
                                     + (g8 & 1) * 16 + kk * 32);
    {
        const int l2g = (lane & 15) >> 3;
        #pragma unroll
        for (int kk = 0; kk < 2; ++kk)
            boffc[kk] = (uint32_t)((nw * 40 + 32 + i8) * AROWB + l2g * 16 + kk * 32);
    }

    float acc[2][5][4];
    #pragma unroll
    for (int mt = 0; mt < 2; ++mt)
        #pragma unroll
        for (int t = 0; t < 5; ++t)
            #pragma unroll
            for (int e = 0; e < 4; ++e) acc[mt][t][e] = 0.f;

    const uint32_t sbA0 = smb + OFF_A0;
    const uint32_t sbA1 = smb + OFF_A0 + A_STAGE;

    // ---- prologue: A(0) in smem, A(1) in regs, B(0..3) in flight ----
    ldgA(0, rcur);
    cpB(0); cpB(1); cpB(2); cpB(3);
    stsA(rcur, sbA0);
    ldgA(1, rcur);
    __syncthreads();                 // A(0) STS visible

    for (int ch = 0; ch < NCH; ++ch) {
        // pending groups entering here: {ch..ch+3}; release when cpB(ch) lands
        asm volatile("cp.async.wait_group 3;");

        if (ch + 2 < NCH) ldgA(ch + 2, rnxt);
        if (ch + 1 < NCH) stsA(rcur, (ch & 1) ? sbA0 : sbA1);  // freed at prev barrier

        const uint32_t sbA = (ch & 1) ? sbA1 : sbA0;
        const uint32_t sbB = smb + OFF_B0 + (uint32_t)(ch % NBST) * B_STAGE;

        #pragma unroll
        for (int kk = 0; kk < 2; ++kk) {
            uint32_t a0[4], a1[4], q0[4], q1[4], q2[2];
            ldsm4(a0, sbA + aoff[0][kk]);
            ldsm4(a1, sbA + aoff[1][kk]);
            ldsm4(q0, sbB + boff[0][kk]);
            ldsm4(q1, sbB + boff[1][kk]);
            ldsm2(q2, sbB + boffc[kk]);
            mma_16x8x16(acc[0][0], a0, q0);
            mma_16x8x16(acc[0][1], a0, q0 + 2);
            mma_16x8x16(acc[0][2], a0, q1);
            mma_16x8x16(acc[0][3], a0, q1 + 2);
            mma_16x8x16(acc[0][4], a0, q2);
            mma_16x8x16(acc[1][0], a1, q0);
            mma_16x8x16(acc[1][1], a1, q0 + 2);
            mma_16x8x16(acc[1][2], a1, q1);
            mma_16x8x16(acc[1][3], a1, q1 + 2);
            mma_16x8x16(acc[1][4], a1, q2);
        }

        __syncthreads();             // stage ch consumed by all warps
        cpB(ch + 4);                 // refill freed B stage (empty group past NCH)
        #pragma unroll
        for (int i = 0; i < 4; ++i) rcur[i] = rnxt[i];
    }

    // ---- accumulators -> smem bases[128][81] ----
    const int qr = lane >> 2, qc = lane & 3;
    float* bases = smf + EPI_BASE_F;
    #pragma unroll
    for (int mt = 0; mt < 2; ++mt) {
        const int r = mw * 32 + mt * 16 + qr;
        #pragma unroll
        for (int t = 0; t < 5; ++t) {
            const int c = nw * 40 + t * 8 + qc * 2;
            bases[(r    ) * BROW + c    ] = acc[mt][t][0];
            bases[(r    ) * BROW + c + 1] = acc[mt][t][1];
            bases[(r + 8) * BROW + c    ] = acc[mt][t][2];
            bases[(r + 8) * BROW + c + 1] = acc[mt][t][3];
        }
    }

    // chain tail weights W[:,1024:1064] + biases (fp32 originals)
    float* wt = smf + EPI_WT_F;
    float* bb = smf + EPI_BB_F;
    for (int idx = tid; idx < 2 * Cc * Cc; idx += THREADS) {
        const int chn = idx / (Cc * Cc);
        const int rem = idx - chn * Cc * Cc;
        const int i = rem / Cc, j = rem % Cc;
        const float* Wp = chn ? Wr : W;
        wt[idx] = Wp[(size_t)i * (Dd + Cc) + Dd + j];
    }
    if (tid < 2 * Cc) bb[tid] = (tid < Cc) ? b[tid] : br[tid - Cc];
    __syncthreads();

    // ---- sequential chains: 256 threads = 128 rows x 2 chains ----
    {
        const int row = tid >> 1, chn = tid & 1;
        float* my        = bases + row * BROW + chn * Cc;
        const float* wtc = wt + chn * Cc * Cc;
        const float* bbc = bb + chn * Cc;
        float s[Cc];
        #pragma unroll
        for (int i = 0; i < Cc; ++i) {
            float x = my[i] + bbc[i];
            #pragma unroll
            for (int j = 0; j < i; ++j)
                x = fmaf(s[j], wtc[i * Cc + j], x);
            s[i] = 1.0f / (1.0f + __expf(-x));
            my[i] = s[i];
        }
    }
    __syncthreads();

    // ---- combine fwd + reversed rev, coalesced store ----
    #pragma unroll
    for (int it = 0; it < (RB * Cc) / THREADS; ++it) {   // 20
        const int idx = tid + it * THREADS;
        const int r = idx / Cc, c = idx - r * Cc;
        const float vf = bases[r * BROW + c];
        const float vr = bases[r * BROW + Cc + (Cc - 1 - c)];
        out[(size_t)(row0 + r) * Cc + c] = 0.5f * (vf + vr);
    }
}

extern "C" void kernel_launch(void* const* d_in, const int* in_sizes, int n_in,
                              void* d_out, int out_size) {
    const float* src = (const float*)d_in[0];
    // d_in[1] = attn_mask (unused)
    const float* W   = (const float*)d_in[2];
    const float* b   = (const float*)d_in[3];
    const float* Wr  = (const float*)d_in[4];
    const float* br  = (const float*)d_in[5];
    float* out = (float*)d_out;

    convert_w<<<(CT * Dd + 255) / 256, 256>>>(W, Wr);
    cudaFuncSetAttribute(bichain_p4,
                         cudaFuncAttributeMaxDynamicSharedMemorySize, SMEM_BYTES);
    bichain_p4<<<Bsz / RB, THREADS, SMEM_BYTES>>>(src, W, b, Wr, br, out);
}

// round 10
// speedup vs baseline: 1.4539x; 1.4533x over previous
#include <cuda_runtime.h>
#include <cuda_fp16.h>
#include <cstdint>

#define Bsz     32768
#define Dd      1024
#define Cc      40
#define CT      80            // 40 fwd + 40 rev output columns
#define RB      128           // rows (M) per CTA -> 256 CTAs
#define THREADS 256           // 8 warps: 4 M-warps x 2 N-warps
#define KC      32            // k per chunk
#define NCH     (Dd / KC)     // 32
#define NST     4             // ring depth (A and B)

#define PADK    40                        // A fp32 floats/row (160B) - LDS.64 conflict-free
#define A_STAGE_B (RB * PADK * 4)         // 20480
#define AROWB   80                        // B fp16 row bytes (64 data + 16 pad) - LDSM conflict-free
#define B_STAGE_B (CT * AROWB)            // 6400
#define OFF_A0  1024
#define OFF_B0  (OFF_A0 + NST * A_STAGE_B)     // 82944
#define SMEM_BYTES (OFF_B0 + NST * B_STAGE_B)  // 108544 -> 2 CTAs/SM

// epilogue overlay (aliases rings after mainloop)
#define BROW    81
#define EPI_BASE_F 256
#define EPI_WT_F   (EPI_BASE_F + RB * BROW)
#define EPI_BB_F   (EPI_WT_F + 2 * Cc * Cc)

__device__ __half Wh[CT * Dd];   // fp16 copy of GEMM part of [W;W_rev]

extern __shared__ float smf[];

__device__ __forceinline__ uint32_t pk(float lo, float hi) {
    uint32_t r;
    asm("cvt.rn.f16x2.f32 %0, %1, %2;" : "=r"(r) : "f"(hi), "f"(lo));
    return r;
}

__device__ __forceinline__ void mma_16x8x16(float* d, const uint32_t* a,
                                            const uint32_t* bf) {
    asm volatile(
        "mma.sync.aligned.m16n8k16.row.col.f32.f16.f16.f32 "
        "{%0,%1,%2,%3}, {%4,%5,%6,%7}, {%8,%9}, {%0,%1,%2,%3};"
        : "+f"(d[0]), "+f"(d[1]), "+f"(d[2]), "+f"(d[3])
        : "r"(a[0]), "r"(a[1]), "r"(a[2]), "r"(a[3]), "r"(bf[0]), "r"(bf[1]));
}

__device__ __forceinline__ void ldsm4(uint32_t* r, uint32_t a) {
    asm volatile("ldmatrix.sync.aligned.m8n8.x4.shared.b16 {%0,%1,%2,%3}, [%4];"
                 : "=r"(r[0]), "=r"(r[1]), "=r"(r[2]), "=r"(r[3]) : "r"(a));
}
__device__ __forceinline__ void ldsm2(uint32_t* r, uint32_t a) {
    asm volatile("ldmatrix.sync.aligned.m8n8.x2.shared.b16 {%0,%1}, [%2];"
                 : "=r"(r[0]), "=r"(r[1]) : "r"(a));
}

__global__ void convert_w(const float* __restrict__ W,
                          const float* __restrict__ Wr) {
    const int idx = blockIdx.x * 256 + threadIdx.x;
    if (idx < CT * Dd) {
        const int r = idx >> 10, k = idx & 1023;
        const float* Wp = (r < Cc) ? W  + (size_t)r        * (Dd + Cc)
                                   : Wr + (size_t)(r - Cc) * (Dd + Cc);
        Wh[idx] = __float2half_rn(Wp[k]);
    }
}

__global__ void __launch_bounds__(THREADS, 2)
bichain_deep(const float* __restrict__ src,
             const float* __restrict__ W,  const float* __restrict__ b,
             const float* __restrict__ Wr, const float* __restrict__ br,
             float* __restrict__ out) {
    const int tid  = threadIdx.x;
    const int warp = tid >> 5;
    const int lane = tid & 31;
    const int row0 = blockIdx.x * RB;

    uint32_t smb;
    asm("{ .reg .u64 t; cvta.to.shared.u64 t, %1; cvt.u32.u64 %0, t; }"
        : "=r"(smb) : "l"(smf));

    // ---- producer thread mapping ----
    // A: 1024 x 16B per chunk; thread handles rows tid>>3 + 32i (i<4), seg tid&7
    const int arow = tid >> 3, aseg = tid & 7;
    const float* gA[4];
    uint32_t dA[4];
    #pragma unroll
    for (int i = 0; i < 4; ++i) {
        gA[i] = src + (size_t)(row0 + arow + 32 * i) * Dd + aseg * 4;
        dA[i] = (uint32_t)((arow + 32 * i) * (PADK * 4) + aseg * 16);
    }
    // B: 320 x 16B per chunk; rows tid>>2 (+64), seg tid&3 (16B = 8 halves)
    const int brow = tid >> 2, bseg = tid & 3;
    const __half* gB0 = Wh + (size_t)brow * Dd + bseg * 8;
    const __half* gB1 = Wh + (size_t)(brow + 64) * Dd + bseg * 8;
    const uint32_t dB0 = (uint32_t)(brow * AROWB + bseg * 16);
    const uint32_t dB1 = (uint32_t)((brow + 64) * AROWB + bseg * 16);

    auto issue = [&](int ch) {
        if (ch < NCH) {
            const uint32_t aS = smb + OFF_A0 + (uint32_t)(ch & 3) * A_STAGE_B;
            const uint32_t bS = smb + OFF_B0 + (uint32_t)(ch & 3) * B_STAGE_B;
            const int k0 = ch * KC;
            #pragma unroll
            for (int i = 0; i < 4; ++i)
                asm volatile("cp.async.cg.shared.global [%0], [%1], 16;"
                             :: "r"(aS + dA[i]), "l"(gA[i] + k0));
            asm volatile("cp.async.ca.shared.global [%0], [%1], 16;"
                         :: "r"(bS + dB0), "l"(gB0 + k0));
            if (tid < 64)
                asm volatile("cp.async.ca.shared.global [%0], [%1], 16;"
                             :: "r"(bS + dB1), "l"(gB1 + k0));
        }
        asm volatile("cp.async.commit_group;");   // uniform accounting
    };

    // ---- consumer offsets ----
    const int mw = warp >> 1, nw = warp & 1;
    const int qr = lane >> 2, qc = lane & 3;
    const int g8 = lane >> 3, i8 = lane & 7;

    int rA2[2][2];                       // A float2 indices (stage-relative)
    #pragma unroll
    for (int mt = 0; mt < 2; ++mt) {
        const int r = mw * 32 + mt * 16 + qr;
        rA2[mt][0] = r * (PADK / 2) + qc;
        rA2[mt][1] = (r + 8) * (PADK / 2) + qc;
    }
    uint32_t boff[2][2], boffc[2];       // B ldmatrix byte offsets (stage-relative)
    #pragma unroll
    for (int p = 0; p < 2; ++p)
        #pragma unroll
        for (int kk = 0; kk < 2; ++kk)
            boff[p][kk] = (uint32_t)((nw * 40 + p * 16 + (g8 >> 1) * 8 + i8) * AROWB
                                     + (g8 & 1) * 16 + kk * 32);
    {
        const int l2g = (lane & 15) >> 3;
        #pragma unroll
        for (int kk = 0; kk < 2; ++kk)
            boffc[kk] = (uint32_t)((nw * 40 + 32 + i8) * AROWB + l2g * 16 + kk * 32);
    }

    float acc[2][5][4];
    #pragma unroll
    for (int mt = 0; mt < 2; ++mt)
        #pragma unroll
        for (int t = 0; t < 5; ++t)
            #pragma unroll
            for (int e = 0; e < 4; ++e) acc[mt][t][e] = 0.f;

    // ---- prologue: 3 chunks in flight ----
    issue(0); issue(1); issue(2);

    for (int ch = 0; ch < NCH; ++ch) {
        // pending groups: {ch, ch+1, ch+2} -> release when chunk ch lands
        asm volatile("cp.async.wait_group 2;");
        __syncthreads();                 // data visible + stage (ch+3)&3 confirmed free
        issue(ch + 3);                   // refill stage freed in iter ch-1

        const float2* Ap2 =
            (const float2*)((const char*)smf + OFF_A0 + (ch & 3) * A_STAGE_B);
        const uint32_t sbB = smb + OFF_B0 + (uint32_t)(ch & 3) * B_STAGE_B;

        #pragma unroll
        for (int kk = 0; kk < 2; ++kk) {
            const int kb2 = kk * 8;
            uint32_t afr[2][4], q0[4], q1[4], q2[2];
            #pragma unroll
            for (int mt = 0; mt < 2; ++mt) {
                float2 p0 = Ap2[rA2[mt][0] + kb2];
                float2 p1 = Ap2[rA2[mt][1] + kb2];
                float2 p2 = Ap2[rA2[mt][0] + kb2 + 4];
                float2 p3 = Ap2[rA2[mt][1] + kb2 + 4];
                afr[mt][0] = pk(p0.x, p0.y);
                afr[mt][1] = pk(p1.x, p1.y);
                afr[mt][2] = pk(p2.x, p2.y);
                afr[mt][3] = pk(p3.x, p3.y);
            }
            ldsm4(q0, sbB + boff[0][kk]);
            ldsm4(q1, sbB + boff[1][kk]);
            ldsm2(q2, sbB + boffc[kk]);
            mma_16x8x16(acc[0][0], afr[0], q0);
            mma_16x8x16(acc[0][1], afr[0], q0 + 2);
            mma_16x8x16(acc[0][2], afr[0], q1);
            mma_16x8x16(acc[0][3], afr[0], q1 + 2);
            mma_16x8x16(acc[0][4], afr[0], q2);
            mma_16x8x16(acc[1][0], afr[1], q0);
            mma_16x8x16(acc[1][1], afr[1], q0 + 2);
            mma_16x8x16(acc[1][2], afr[1], q1);
            mma_16x8x16(acc[1][3], afr[1], q1 + 2);
            mma_16x8x16(acc[1][4], afr[1], q2);
        }
    }
    __syncthreads();   // last stage consumed everywhere before overlay writes

    // ---- accumulators -> smem bases[128][81] ----
    float* bases = smf + EPI_BASE_F;
    #pragma unroll
    for (int mt = 0; mt < 2; ++mt) {
        const int r = mw * 32 + mt * 16 + qr;
        #pragma unroll
        for (int t = 0; t < 5; ++t) {
            const int c = nw * 40 + t * 8 + qc * 2;
            bases[(r    ) * BROW + c    ] = acc[mt][t][0];
            bases[(r    ) * BROW + c + 1] = acc[mt][t][1];
            bases[(r + 8) * BROW + c    ] = acc[mt][t][2];
            bases[(r + 8) * BROW + c + 1] = acc[mt][t][3];
        }
    }

    // chain tail weights W[:,1024:1064] + biases (fp32 originals)
    float* wt = smf + EPI_WT_F;
    float* bb = smf + EPI_BB_F;
    for (int idx = tid; idx < 2 * Cc * Cc; idx += THREADS) {
        const int chn = idx / (Cc * Cc);
        const int rem = idx - chn * Cc * Cc;
        const int i = rem / Cc, j = rem % Cc;
        const float* Wp = chn ? Wr : W;
        wt[idx] = Wp[(size_t)i * (Dd + Cc) + Dd + j];
    }
    if (tid < 2 * Cc) bb[tid] = (tid < Cc) ? b[tid] : br[tid - Cc];
    __syncthreads();

    // ---- sequential chains: 256 threads = 128 rows x 2 chains ----
    {
        const int row = tid >> 1, chn = tid & 1;
        float* my        = bases + row * BROW + chn * Cc;
        const float* wtc = wt + chn * Cc * Cc;
        const float* bbc = bb + chn * Cc;
        float s[Cc];
        #pragma unroll
        for (int i = 0; i < Cc; ++i) {
            float x = my[i] + bbc[i];
            #pragma unroll
            for (int j = 0; j < i; ++j)
                x = fmaf(s[j], wtc[i * Cc + j], x);
            s[i] = 1.0f / (1.0f + __expf(-x));
            my[i] = s[i];
        }
    }
    __syncthreads();

    // ---- combine fwd + reversed rev, coalesced store ----
    #pragma unroll
    for (int it = 0; it < (RB * Cc) / THREADS; ++it) {   // 20
        const int idx = tid + it * THREADS;
        const int r = idx / Cc, c = idx - r * Cc;
        const float vf = bases[r * BROW + c];
        const float vr = bases[r * BROW + Cc + (Cc - 1 - c)];
        out[(size_t)(row0 + r) * Cc + c] = 0.5f * (vf + vr);
    }
}

extern "C" void kernel_launch(void* const* d_in, const int* in_sizes, int n_in,
                              void* d_out, int out_size) {
    const float* src = (const float*)d_in[0];
    // d_in[1] = attn_mask (unused)
    const float* W   = (const float*)d_in[2];
    const float* b   = (const float*)d_in[3];
    const float* Wr  = (const float*)d_in[4];
    const float* br  = (const float*)d_in[5];
    float* out = (float*)d_out;

    convert_w<<<(CT * Dd + 255) / 256, 256>>>(W, Wr);
    cudaFuncSetAttribute(bichain_deep,
                         cudaFuncAttributeMaxDynamicSharedMemorySize, SMEM_BYTES);
    bichain_deep<<<Bsz / RB, THREADS, SMEM_BYTES>>>(src, W, b, Wr, br, out);
}